// round 9
// baseline (speedup 1.0000x reference)
#include <cuda_runtime.h>

// xg scratch: [B=32][T=2048][4H=1024] fp32 = 256 MB
__device__ float g_xg[32ull * 2048ull * 1024ull];

// ---------------- f32x2 helpers (sm_103a packed fp32) ----------------
__device__ __forceinline__ void fma2(unsigned long long &acc,
                                     unsigned long long a,
                                     unsigned long long b) {
    asm("fma.rn.f32x2 %0, %1, %2, %0;" : "+l"(acc) : "l"(a), "l"(b));
}
__device__ __forceinline__ unsigned long long splat2(float x) {
    unsigned long long r;
    unsigned xu = __float_as_uint(x);
    asm("mov.b64 %0, {%1, %1};" : "=l"(r) : "r"(xu));
    return r;
}
__device__ __forceinline__ float hadd2(unsigned long long v) {
    float lo, hi;
    asm("mov.b64 {%0, %1}, %2;" : "=f"(lo), "=f"(hi) : "l"(v));
    return lo + hi;
}
__device__ __forceinline__ float sigf(float x) {
    return __fdividef(1.f, 1.f + __expf(-x));
}
__device__ __forceinline__ float tanhf_fast(float x) {
    return __fdividef(2.f, 1.f + __expf(-2.f * x)) - 1.f;
}
__device__ __forceinline__ unsigned smem_u32(const void* p) {
    return (unsigned)__cvta_generic_to_shared(p);
}

// mbarrier primitives
__device__ __forceinline__ void mbar_init(unsigned mbar, unsigned cnt) {
    asm volatile("mbarrier.init.shared.b64 [%0], %1;" :: "r"(mbar), "r"(cnt) : "memory");
}
__device__ __forceinline__ void mbar_arm_tx(unsigned mbar, unsigned bytes) {
    asm volatile("mbarrier.arrive.expect_tx.shared.b64 _, [%0], %1;"
                 :: "r"(mbar), "r"(bytes) : "memory");
}
__device__ __forceinline__ void mbar_wait(unsigned mbar, unsigned parity) {
    unsigned done;
    asm volatile(
        "{\n\t.reg .pred p;\n\t"
        "mbarrier.try_wait.parity.acquire.cta.shared::cta.b64 p, [%1], %2;\n\t"
        "selp.b32 %0, 1, 0, p;\n\t}"
        : "=r"(done) : "r"(mbar), "r"(parity) : "memory");
    while (!done) {
        asm volatile(
            "{\n\t.reg .pred p;\n\t"
            "mbarrier.try_wait.parity.acquire.cta.shared::cta.b64 p, [%1], %2, 0x989680;\n\t"
            "selp.b32 %0, 1, 0, p;\n\t}"
            : "=r"(done) : "r"(mbar), "r"(parity) : "memory");
    }
}
// 16B remote store + tx-signal, with PRE-MAPPED remote addresses
__device__ __forceinline__ void st_async_v4_pre(unsigned ra, unsigned rb,
                                                float4 v) {
    asm volatile(
        "st.async.shared::cluster.mbarrier::complete_tx::bytes.v4.b32 "
        "[%0], {%2, %3, %4, %5}, [%1];"
        :: "r"(ra), "r"(rb),
           "r"(__float_as_uint(v.x)), "r"(__float_as_uint(v.y)),
           "r"(__float_as_uint(v.z)), "r"(__float_as_uint(v.w)) : "memory");
}

// =====================================================================
// Phase 1: xg[m][g] = relu(x)[m][:] . W_ih[g][:] + b_ih[g] + b_hh[g]
// (FMA-bound, ~0.7 ms, not the bottleneck)
// =====================================================================
__global__ __launch_bounds__(256, 2) void p1_gemm(
    const float* __restrict__ x, const float* __restrict__ Wih,
    const float* __restrict__ bih, const float* __restrict__ bhh)
{
    __shared__ __align__(16) float Asm[16][132];  // [k][m]
    __shared__ __align__(16) float Wsm[16][132];  // [k][g]

    const int t  = threadIdx.x;
    const int tx = t & 15, ty = t >> 4;
    const int mb = blockIdx.y * 128;
    const int gb = blockIdx.x * 128;

    unsigned long long acc[4][8];
    #pragma unroll
    for (int p = 0; p < 4; p++)
        #pragma unroll
        for (int g = 0; g < 8; g++) acc[p][g] = 0ull;

    for (int kb = 0; kb < 256; kb += 16) {
        #pragma unroll
        for (int i = 0; i < 2; i++) {
            int idx = t + i * 256;
            int m   = idx >> 2;
            int kc  = (idx & 3) << 2;
            float4 av = *(const float4*)(x + (size_t)(mb + m) * 256 + kb + kc);
            Asm[kc + 0][m] = fmaxf(av.x, 0.f);
            Asm[kc + 1][m] = fmaxf(av.y, 0.f);
            Asm[kc + 2][m] = fmaxf(av.z, 0.f);
            Asm[kc + 3][m] = fmaxf(av.w, 0.f);
            float4 wv = *(const float4*)(Wih + (size_t)(gb + m) * 256 + kb + kc);
            Wsm[kc + 0][m] = wv.x;
            Wsm[kc + 1][m] = wv.y;
            Wsm[kc + 2][m] = wv.z;
            Wsm[kc + 3][m] = wv.w;
        }
        __syncthreads();
        #pragma unroll
        for (int k = 0; k < 16; k++) {
            ulonglong2 a01 = *(const ulonglong2*)&Asm[k][ty * 8];
            ulonglong2 a23 = *(const ulonglong2*)&Asm[k][ty * 8 + 4];
            float4 w0 = *(const float4*)&Wsm[k][tx * 8];
            float4 w1 = *(const float4*)&Wsm[k][tx * 8 + 4];
            float wf[8] = {w0.x, w0.y, w0.z, w0.w, w1.x, w1.y, w1.z, w1.w};
            #pragma unroll
            for (int g = 0; g < 8; g++) {
                unsigned long long ws = splat2(wf[g]);
                fma2(acc[0][g], a01.x, ws);
                fma2(acc[1][g], a01.y, ws);
                fma2(acc[2][g], a23.x, ws);
                fma2(acc[3][g], a23.y, ws);
            }
        }
        __syncthreads();
    }

    float bs[8];
    {
        const float4* bi = (const float4*)(bih + gb + tx * 8);
        const float4* bh = (const float4*)(bhh + gb + tx * 8);
        float4 b0 = bi[0], b1 = bi[1], c0 = bh[0], c1 = bh[1];
        bs[0] = b0.x + c0.x; bs[1] = b0.y + c0.y; bs[2] = b0.z + c0.z; bs[3] = b0.w + c0.w;
        bs[4] = b1.x + c1.x; bs[5] = b1.y + c1.y; bs[6] = b1.z + c1.z; bs[7] = b1.w + c1.w;
    }
    #pragma unroll
    for (int p = 0; p < 4; p++) {
        float lo[8], hi[8];
        #pragma unroll
        for (int g = 0; g < 8; g++) {
            float l, h;
            asm("mov.b64 {%0, %1}, %2;" : "=f"(l), "=f"(h) : "l"(acc[p][g]));
            lo[g] = l + bs[g];
            hi[g] = h + bs[g];
        }
        size_t m0 = (size_t)(mb + ty * 8 + 2 * p);
        float* r0 = g_xg + m0 * 1024 + gb + tx * 8;
        float* r1 = r0 + 1024;
        *(float4*)(r0)     = make_float4(lo[0], lo[1], lo[2], lo[3]);
        *(float4*)(r0 + 4) = make_float4(lo[4], lo[5], lo[6], lo[7]);
        *(float4*)(r1)     = make_float4(hi[0], hi[1], hi[2], hi[3]);
        *(float4*)(r1 + 4) = make_float4(hi[4], hi[5], hi[6], hi[7]);
    }
}

// =====================================================================
// Phase 2: recurrence, TWO interleaved batch pipelines per cluster.
// 16 clusters x 8 CTAs; cluster handles batches {2c, 2c+1} as
// independent pipelines A and B sharing the register-resident W_hh.
// While warp0 runs A's update+sends, warps 1-7 run B's matvec (and
// vice versa) -> wire/arrival/MUFU latency hidden behind compute.
// =====================================================================
__global__ __launch_bounds__(256, 1) __cluster_dims__(8, 1, 1)
void p2_lstm(const float* __restrict__ Whh, float* __restrict__ out)
{
    __shared__ __align__(16) float hA[2][256];        // [buf][k]
    __shared__ __align__(16) float hB[2][256];
    __shared__ __align__(16) float ring[4][256];      // xg [slot][b*128+gt*32+j]
    __shared__ __align__(8)  float redA[2][128];      // [kh][row]
    __shared__ __align__(8)  float redB[2][128];
    __shared__ __align__(8)  unsigned long long barA[2], barB[2];

    unsigned rank;
    asm("mov.u32 %0, %%cluster_ctarank;" : "=r"(rank));
    const int t   = threadIdx.x;
    const int row = t & 127;
    const int kh  = t >> 7;
    const int gt  = row >> 5;
    const int j   = row & 31;
    const int G   = gt * 256 + (int)rank * 32 + j;   // global gate row
    const int b0  = (blockIdx.x >> 3) * 2;

    // persistent weights: 64 x f32x2 in registers (k = kh*128 + 2p)
    unsigned long long w2[64];
    {
        const unsigned long long* wp =
            (const unsigned long long*)(Whh + (size_t)G * 256 + kh * 128);
        #pragma unroll
        for (int i = 0; i < 64; i++) w2[i] = wp[i];
    }

    for (int i = t; i < 512; i += 256) ((float*)hA)[i] = 0.f;
    for (int i = t; i < 512; i += 256) ((float*)hB)[i] = 0.f;

    // xg ring loader: thread t covers (b = t>>7, gate g2 = (t>>5)&3, j2 = t&31)
    const float* xg_ld = g_xg
        + (size_t)(b0 + (t >> 7)) * 2048 * 1024
        + (size_t)(((t >> 5) & 3) * 256 + (int)rank * 32 + (t & 31));
    ring[0][t] = xg_ld[0];
    ring[1][t] = xg_ld[1024];
    float pend = xg_ld[2 * 1024];

    const unsigned anchor = smem_u32(&hA[0][0]);
    const unsigned barA0_a = smem_u32(&barA[0]);
    const unsigned barA1_a = smem_u32(&barA[1]);
    const unsigned barB0_a = smem_u32(&barB[0]);
    const unsigned barB1_a = smem_u32(&barB[1]);
    if (t == 0) {
        mbar_init(barA0_a, 1); mbar_init(barA1_a, 1);
        mbar_init(barB0_a, 1); mbar_init(barB1_a, 1);
    }
    // pre-mapped per-rank remote base (offsets within CTA window add linearly)
    unsigned rbase[8];
    #pragma unroll
    for (int r = 0; r < 8; r++)
        asm("mapa.shared::cluster.u32 %0, %1, %2;"
            : "=r"(rbase[r]) : "r"(anchor), "r"(r));

    __syncthreads();
    asm volatile("barrier.cluster.arrive.aligned;" ::: "memory");
    asm volatile("barrier.cluster.wait.aligned;"   ::: "memory");
    if (t == 0) {
        mbar_arm_tx(barA0_a, 1024); mbar_arm_tx(barA1_a, 1024);
        mbar_arm_tx(barB0_a, 1024); mbar_arm_tx(barB1_a, 1024);
    }

    float c_state = 0.f;                       // per update thread (t<64)
    unsigned phA0 = 0, phA1 = 0, phB0 = 0, phB1 = 0;
    const int uj = t & 31;                     // update lane (within warp)
    float* outA = out + (size_t)(b0)     * 2048 * 256 + (int)rank * 32 + uj;
    float* outB = out + (size_t)(b0 + 1) * 2048 * 256 + (int)rank * 32 + uj;

    for (int s = 0; s < 2048; s++) {
        const int rb = s & 1;
        const int wb = rb ^ 1;

        // xg pipeline: store s+2 (loaded last iter), start load for s+3
        ring[(s + 2) & 3][t] = pend;
        {
            int ps = s + 3; if (ps > 2047) ps = 2047;
            pend = xg_ld[(size_t)ps * 1024];
        }

        // ================= pipeline A =================
        if (s > 0) {
            if (rb) { mbar_wait(barA1_a, phA1); phA1 ^= 1; if (t == 0) mbar_arm_tx(barA1_a, 1024); }
            else    { mbar_wait(barA0_a, phA0); phA0 ^= 1; if (t == 0) mbar_arm_tx(barA0_a, 1024); }
        }
        {
            unsigned long long a0 = 0, a1 = 0, a2 = 0, a3 = 0;
            const ulonglong2* hp = (const ulonglong2*)&hA[rb][kh << 7];
            #pragma unroll
            for (int q = 0; q < 32; q += 2) {
                ulonglong2 h0 = hp[q];
                ulonglong2 h1 = hp[q + 1];
                fma2(a0, w2[2 * q],     h0.x);
                fma2(a1, w2[2 * q + 1], h0.y);
                fma2(a2, w2[2 * q + 2], h1.x);
                fma2(a3, w2[2 * q + 3], h1.y);
            }
            unsigned long long s01, s23;
            asm("add.rn.f32x2 %0, %1, %2;" : "=l"(s01) : "l"(a0), "l"(a1));
            asm("add.rn.f32x2 %0, %1, %2;" : "=l"(s23) : "l"(a2), "l"(a3));
            asm("add.rn.f32x2 %0, %1, %2;" : "=l"(s01) : "l"(s01), "l"(s23));
            redA[kh][row] = hadd2(s01);
        }
        __syncthreads();   // redA ready; also closes redB reads of iter s-1

        if (t < 32) {      // warp 0: batch A epilogue (overlaps others' waitB+matvecB)
            const float* xr = &ring[s & 3][uj];
            float gi = redA[0][      uj] + redA[1][      uj] + xr[0];
            float gf = redA[0][ 32 + uj] + redA[1][ 32 + uj] + xr[32];
            float gg = redA[0][ 64 + uj] + redA[1][ 64 + uj] + xr[64];
            float go = redA[0][ 96 + uj] + redA[1][ 96 + uj] + xr[96];
            float iv = sigf(gi), fv = sigf(gf);
            float gv = tanhf_fast(gg), ov = sigf(go);
            c_state = fv * c_state + iv * gv;
            float h = ov * tanhf_fast(c_state);

            float4 hv;
            hv.x = h;
            hv.y = __shfl_down_sync(0xffffffffu, h, 1);
            hv.z = __shfl_down_sync(0xffffffffu, h, 2);
            hv.w = __shfl_down_sync(0xffffffffu, h, 3);
            if (s < 2047 && (uj & 3) == 0) {
                unsigned dd = smem_u32(&hA[wb][(int)rank * 32 + uj]) - anchor;
                unsigned db = (wb ? barA1_a : barA0_a) - anchor;
                #pragma unroll
                for (int r = 0; r < 8; r++)
                    st_async_v4_pre(rbase[r] + dd, rbase[r] + db, hv);
            }
            outA[(size_t)s * 256] = h;
        }

        // ================= pipeline B =================
        if (s > 0) {
            if (rb) { mbar_wait(barB1_a, phB1); phB1 ^= 1; if (t == 0) mbar_arm_tx(barB1_a, 1024); }
            else    { mbar_wait(barB0_a, phB0); phB0 ^= 1; if (t == 0) mbar_arm_tx(barB0_a, 1024); }
        }
        {
            unsigned long long a0 = 0, a1 = 0, a2 = 0, a3 = 0;
            const ulonglong2* hp = (const ulonglong2*)&hB[rb][kh << 7];
            #pragma unroll
            for (int q = 0; q < 32; q += 2) {
                ulonglong2 h0 = hp[q];
                ulonglong2 h1 = hp[q + 1];
                fma2(a0, w2[2 * q],     h0.x);
                fma2(a1, w2[2 * q + 1], h0.y);
                fma2(a2, w2[2 * q + 2], h1.x);
                fma2(a3, w2[2 * q + 3], h1.y);
            }
            unsigned long long s01, s23;
            asm("add.rn.f32x2 %0, %1, %2;" : "=l"(s01) : "l"(a0), "l"(a1));
            asm("add.rn.f32x2 %0, %1, %2;" : "=l"(s23) : "l"(a2), "l"(a3));
            asm("add.rn.f32x2 %0, %1, %2;" : "=l"(s01) : "l"(s01), "l"(s23));
            redB[kh][row] = hadd2(s01);
        }
        __syncthreads();   // redB ready; also closes redA reads (warp 0 joined)

        if (t >= 32 && t < 64) {   // warp 1: batch B epilogue (overlaps next matvecA)
            const float* xr = &ring[s & 3][128 + uj];
            float gi = redB[0][      uj] + redB[1][      uj] + xr[0];
            float gf = redB[0][ 32 + uj] + redB[1][ 32 + uj] + xr[32];
            float gg = redB[0][ 64 + uj] + redB[1][ 64 + uj] + xr[64];
            float go = redB[0][ 96 + uj] + redB[1][ 96 + uj] + xr[96];
            float iv = sigf(gi), fv = sigf(gf);
            float gv = tanhf_fast(gg), ov = sigf(go);
            c_state = fv * c_state + iv * gv;
            float h = ov * tanhf_fast(c_state);

            float4 hv;
            hv.x = h;
            hv.y = __shfl_down_sync(0xffffffffu, h, 1);
            hv.z = __shfl_down_sync(0xffffffffu, h, 2);
            hv.w = __shfl_down_sync(0xffffffffu, h, 3);
            if (s < 2047 && (uj & 3) == 0) {
                unsigned dd = smem_u32(&hB[wb][(int)rank * 32 + uj]) - anchor;
                unsigned db = (wb ? barB1_a : barB0_a) - anchor;
                #pragma unroll
                for (int r = 0; r < 8; r++)
                    st_async_v4_pre(rbase[r] + dd, rbase[r] + db, hv);
            }
            outB[(size_t)s * 256] = h;
        }
    }

    asm volatile("barrier.cluster.arrive.aligned;" ::: "memory");
    asm volatile("barrier.cluster.wait.aligned;"   ::: "memory");
}

// =====================================================================
extern "C" void kernel_launch(void* const* d_in, const int* in_sizes, int n_in,
                              void* d_out, int out_size) {
    (void)in_sizes; (void)n_in; (void)out_size;
    const float* x   = (const float*)d_in[0];
    const float* Wih = (const float*)d_in[1];
    const float* Whh = (const float*)d_in[2];
    const float* bih = (const float*)d_in[3];
    const float* bhh = (const float*)d_in[4];
    float* out = (float*)d_out;

    dim3 g1(8, 512);
    p1_gemm<<<g1, 256>>>(x, Wih, bih, bhh);
    p2_lstm<<<128, 256>>>(Whh, out);   // 16 clusters of 8 CTAs
}